// round 9
// baseline (speedup 1.0000x reference)
#include <cuda_runtime.h>
#include <math.h>
#include <cstdint>

// Problem constants
#define PB 2
#define PL 2048
#define PE 2048
#define PH 16
#define PHD 128

// Scratch (device globals: no allocation allowed in kernel_launch)
__device__ float g_q[PB * PH * PL * PHD];        // [B, H, L, HD] (roped, tf32-rounded)
__device__ float g_k[PB * PH * PL * PHD];
__device__ float g_v[PB * PH * PL * PHD];
__device__ float g_y[PB * PL * PE];              // attention out (tf32-rounded)
__device__ float g_xr[PB * PL * PE];             // tf32-rounded x
__device__ float g_war[3 * PE * PE];             // tf32-rounded w_attn
__device__ float g_wpr[PE * PE];                 // tf32-rounded w_proj

// ---------------------------------------------------------------------------
// Helpers
// ---------------------------------------------------------------------------
__device__ __forceinline__ uint32_t smem_u32(const void* p) {
    uint32_t a;
    asm("{ .reg .u64 t; cvta.to.shared.u64 t, %1; cvt.u32.u64 %0, t; }" : "=r"(a) : "l"(p));
    return a;
}

__device__ __forceinline__ float to_tf32(float x) {
    uint32_t u;
    asm("cvt.rna.tf32.f32 %0, %1;" : "=r"(u) : "f"(x));
    return __uint_as_float(u);
}

__device__ __forceinline__ void cp_async16(uint32_t dst, const void* src) {
    asm volatile("cp.async.cg.shared.global [%0], [%1], 16;" :: "r"(dst), "l"(src));
}
__device__ __forceinline__ void cp_commit() {
    asm volatile("cp.async.commit_group;" ::: "memory");
}
template <int N>
__device__ __forceinline__ void cp_wait() {
    asm volatile("cp.async.wait_group %0;" :: "n"(N) : "memory");
}

__device__ __forceinline__ void mma_tf32_16n8k8(
    float& c0, float& c1, float& c2, float& c3,
    uint32_t a0, uint32_t a1, uint32_t a2, uint32_t a3,
    uint32_t b0, uint32_t b1)
{
    asm volatile(
        "mma.sync.aligned.m16n8k8.row.col.f32.tf32.tf32.f32 "
        "{%0,%1,%2,%3}, {%4,%5,%6,%7}, {%8,%9}, {%0,%1,%2,%3};"
        : "+f"(c0), "+f"(c1), "+f"(c2), "+f"(c3)
        : "r"(a0), "r"(a1), "r"(a2), "r"(a3), "r"(b0), "r"(b1));
}

// ---------------------------------------------------------------------------
// tf32 rounding pass
// ---------------------------------------------------------------------------
__global__ __launch_bounds__(256) void round_tf32_kernel(
    const float4* __restrict__ in, float4* __restrict__ out, int n4)
{
    int i = blockIdx.x * blockDim.x + threadIdx.x;
    if (i < n4) {
        float4 v = in[i];
        v.x = to_tf32(v.x); v.y = to_tf32(v.y);
        v.z = to_tf32(v.z); v.w = to_tf32(v.w);
        out[i] = v;
    }
}

// ---------------------------------------------------------------------------
// Shared tf32 HMMA GEMM core (NT): acc += A[bm:bm+128, :] * B[bn:bn+128, :]^T
// 128x128 CTA tile, BK=32, 256 threads, warp 64x32, 2-stage cp.async.
// Prefetch issued mid-compute (ks=0); per-mt A-frag loads interleaved w/ MMAs.
// ---------------------------------------------------------------------------
#define BM 128
#define BN 128
#define BK 32
#define BKP 36
#define TILE_FLOATS (128 * BKP)
#define GEMM_SMEM (4 * TILE_FLOATS * 4)

__device__ __forceinline__ void gemm_core(
    const float* __restrict__ A, const float* __restrict__ B, int K,
    float* sA, float* sB, int bm, int bn, int tid,
    int wm, int wn, int g, int tg, float acc[4][4][4])
{
    const uint32_t sAu = smem_u32(sA);
    const uint32_t sBu = smem_u32(sB);
    const int nt = K >> 5;

    const float* agp[4];
    const float* bgp[4];
    uint32_t asp[4];
#pragma unroll
    for (int j = 0; j < 4; ++j) {
        int c = tid + 256 * j;
        int row = c >> 3, k4 = c & 7;
        agp[j] = A + (size_t)(bm + row) * K + k4 * 4;
        bgp[j] = B + (size_t)(bn + row) * K + k4 * 4;
        asp[j] = (uint32_t)(row * BKP + k4 * 4) * 4;
    }

    // stage 0
#pragma unroll
    for (int j = 0; j < 4; ++j) {
        cp_async16(sAu + asp[j], agp[j]);
        cp_async16(sBu + asp[j], bgp[j]);
    }
    cp_commit();

    const float* aw0 = sA + (wm * 64 + g) * BKP + tg;
    const float* bw0 = sB + (wn * 32 + g) * BKP + tg;

    for (int t = 0; t < nt; ++t) {
        cp_wait<0>();
        __syncthreads();
        const int buf = t & 1;
        const float* At = aw0 + buf * TILE_FLOATS;
        const float* Bt = bw0 + buf * TILE_FLOATS;

#pragma unroll
        for (int ks = 0; ks < 4; ++ks) {
            const int k0 = ks * 8;
            uint32_t bf[4][2];
#pragma unroll
            for (int n = 0; n < 4; ++n) {
                const float* bp = Bt + n * 8 * BKP + k0;
                bf[n][0] = __float_as_uint(bp[0]);
                bf[n][1] = __float_as_uint(bp[4]);
            }
            if (ks == 0 && t + 1 < nt) {
                const uint32_t so = (buf ^ 1) * TILE_FLOATS * 4;
                const size_t go = (size_t)(t + 1) * BK;
#pragma unroll
                for (int j = 0; j < 4; ++j) {
                    cp_async16(sAu + so + asp[j], agp[j] + go);
                    cp_async16(sBu + so + asp[j], bgp[j] + go);
                }
                cp_commit();
            }
#pragma unroll
            for (int mt = 0; mt < 4; ++mt) {
                const float* ap = At + mt * 16 * BKP + k0;
                uint32_t a0 = __float_as_uint(ap[0]);
                uint32_t a1 = __float_as_uint(ap[8 * BKP]);
                uint32_t a2 = __float_as_uint(ap[4]);
                uint32_t a3 = __float_as_uint(ap[8 * BKP + 4]);
#pragma unroll
                for (int n = 0; n < 4; ++n)
                    mma_tf32_16n8k8(acc[mt][n][0], acc[mt][n][1],
                                    acc[mt][n][2], acc[mt][n][3],
                                    a0, a1, a2, a3, bf[n][0], bf[n][1]);
            }
        }
        __syncthreads();
    }
}

// ---------------------------------------------------------------------------
// Plain GEMM (used for output projection)
// ---------------------------------------------------------------------------
__global__ __launch_bounds__(256, 2) void gemm_mma(
    const float* __restrict__ A, const float* __restrict__ B, float* __restrict__ C,
    int M, int N, int K)
{
    extern __shared__ __align__(16) float smg[];
    float* sA = smg;
    float* sB = smg + 2 * TILE_FLOATS;

    const int tid = threadIdx.x;
    const int wid = tid >> 5;
    const int lane = tid & 31;
    const int bm = blockIdx.y * BM;
    const int bn = blockIdx.x * BN;
    const int wm = wid >> 2;
    const int wn = wid & 3;
    const int g = lane >> 2;
    const int tg = lane & 3;

    float acc[4][4][4];
#pragma unroll
    for (int i = 0; i < 4; ++i)
#pragma unroll
        for (int j = 0; j < 4; ++j)
#pragma unroll
            for (int q = 0; q < 4; ++q) acc[i][j][q] = 0.f;

    gemm_core(A, B, K, sA, sB, bm, bn, tid, wm, wn, g, tg, acc);

#pragma unroll
    for (int mt = 0; mt < 4; ++mt) {
        const int row0 = bm + wm * 64 + mt * 16 + g;
#pragma unroll
        for (int nti = 0; nti < 4; ++nti) {
            const int col = bn + wn * 32 + nti * 8 + 2 * tg;
            *(float2*)&C[(size_t)row0 * N + col] =
                make_float2(acc[mt][nti][0], acc[mt][nti][1]);
            *(float2*)&C[(size_t)(row0 + 8) * N + col] =
                make_float2(acc[mt][nti][2], acc[mt][nti][3]);
        }
    }
}

// ---------------------------------------------------------------------------
// QKV GEMM with fused RoPE + head-split + tf32-round epilogue.
// A = x_rounded [4096, 2048], B = w_attn_rounded [6144, 2048].
// N-tile (128 cols) is exactly one (matrix, head): mat = bn>>11, h = (bn&2047)>>7.
// Writes q/k/v in [B, H, L, HD]; q,k roped; all tf32-rounded.
// ---------------------------------------------------------------------------
__global__ __launch_bounds__(256, 2) void gemm_qkv_fused(
    const float* __restrict__ A, const float* __restrict__ B,
    const float* __restrict__ rope,
    float* __restrict__ q, float* __restrict__ k, float* __restrict__ v)
{
    extern __shared__ __align__(16) float smg[];
    float* sA = smg;
    float* sB = smg + 2 * TILE_FLOATS;

    const int tid = threadIdx.x;
    const int wid = tid >> 5;
    const int lane = tid & 31;
    const int bm = blockIdx.y * BM;
    const int bn = blockIdx.x * BN;
    const int wm = wid >> 2;
    const int wn = wid & 3;
    const int g = lane >> 2;
    const int tg = lane & 3;

    float acc[4][4][4];
#pragma unroll
    for (int i = 0; i < 4; ++i)
#pragma unroll
        for (int j = 0; j < 4; ++j)
#pragma unroll
            for (int qq = 0; qq < 4; ++qq) acc[i][j][qq] = 0.f;

    gemm_core(A, B, PE, sA, sB, bm, bn, tid, wm, wn, g, tg, acc);

    const int mat = bn >> 11;                  // 0=q, 1=k, 2=v
    const int hh  = (bn & 2047) >> 7;          // head
    float* dst = (mat == 0) ? q : ((mat == 1) ? k : v);

#pragma unroll
    for (int mt = 0; mt < 4; ++mt) {
        const int row0 = bm + wm * 64 + mt * 16 + g;
#pragma unroll
        for (int half = 0; half < 2; ++half) {
            const int row = row0 + 8 * half;
            const int l = row & (PL - 1);
            const int bb = row >> 11;
            const size_t obase = ((size_t)((bb * PH + hh) * PL + l)) * PHD;
#pragma unroll
            for (int nti = 0; nti < 4; ++nti) {
                const int col = bn + wn * 32 + nti * 8 + 2 * tg;
                const int d = col & 127;
                float c0 = acc[mt][nti][2 * half];
                float c1 = acc[mt][nti][2 * half + 1];
                float o0, o1;
                if (mat < 2) {
                    float2 sc = *(const float2*)&rope[(size_t)(l * 64 + (d >> 1)) * 2];
                    o0 = c0 * sc.y - c1 * sc.x;   // *cos - *sin
                    o1 = c1 * sc.y + c0 * sc.x;
                } else {
                    o0 = c0; o1 = c1;
                }
                *(float2*)&dst[obase + d] = make_float2(to_tf32(o0), to_tf32(o1));
            }
        }
    }
}

// ---------------------------------------------------------------------------
// Flash attention (causal) with tf32 HMMA (unchanged from R7, passing).
// ---------------------------------------------------------------------------
#define AQ_ST 132
#define AK_ST 132
#define AV_ST 136
#define AP_ST 68
#define SQ_F  (128 * AQ_ST)
#define SK_F  (64 * AK_ST)
#define SV_F  (64 * AV_ST)
#define SP_F  (128 * AP_ST)
#define OFF_Q  0
#define OFF_K0 (SQ_F)
#define OFF_K1 (SQ_F + SK_F)
#define OFF_V  (SQ_F + 2 * SK_F)
#define OFF_P  (SQ_F + 2 * SK_F + SV_F)
#define ATT_SMEM ((OFF_P + SP_F) * 4)  // 204800 bytes

__global__ __launch_bounds__(256, 1) void attn_mma_kernel(
    const float* __restrict__ Q, const float* __restrict__ K,
    const float* __restrict__ V, float* __restrict__ Y)
{
    extern __shared__ __align__(16) float smf[];
    const uint32_t sb = smem_u32(smf);
    float* sQ = smf + OFF_Q;
    float* sV = smf + OFF_V;
    float* sP = smf + OFF_P;

    const int qt = gridDim.x - 1 - blockIdx.x;   // heavy CTAs first
    const int h  = blockIdx.y;
    const int b  = blockIdx.z;
    const int tid = threadIdx.x;
    const int wid = tid >> 5;
    const int lane = tid & 31;
    const int g = lane >> 2;
    const int tg = lane & 3;
    const int qbase = qt * 128;
    const size_t hb = ((size_t)(b * PH + h)) * PL * PHD;
    const int nkt = 2 * qt + 2;

    const float* Kbase = K + hb;
    const float* Vbase = V + hb;

    // ---- prologue loads ----
    {
        const float* qsrc = Q + hb + (size_t)qbase * PHD;
#pragma unroll
        for (int j = 0; j < 16; ++j) {
            int c = tid + 256 * j;
            int row = c >> 5, k4 = (c & 31) * 4;
            cp_async16(sb + (uint32_t)(OFF_Q + row * AQ_ST + k4) * 4,
                       qsrc + (size_t)row * PHD + k4);
        }
#pragma unroll
        for (int j = 0; j < 8; ++j) {
            int c = tid + 256 * j;
            int row = c >> 5, k4 = (c & 31) * 4;
            cp_async16(sb + (uint32_t)(OFF_K0 + row * AK_ST + k4) * 4,
                       Kbase + (size_t)row * PHD + k4);
        }
        cp_commit();   // group: {Q, K0}
#pragma unroll
        for (int j = 0; j < 8; ++j) {
            int c = tid + 256 * j;
            int row = c >> 5, k4 = (c & 31) * 4;
            cp_async16(sb + (uint32_t)(OFF_V + row * AV_ST + k4) * 4,
                       Vbase + (size_t)row * PHD + k4);
        }
        cp_commit();   // group: {V0}
    }

    const float scale = 0.08838834764831845f;   // 1/sqrt(128)

    float oacc[16][4];
#pragma unroll
    for (int i = 0; i < 16; ++i)
#pragma unroll
        for (int j = 0; j < 4; ++j) oacc[i][j] = 0.f;
    float m0 = -1e30f, m1 = -1e30f, l0 = 0.f, l1 = 0.f;

    const int wrow = wid * 16;
    const float* aQ = sQ + (wrow + g) * AQ_ST + tg;
    const float* aP = sP + (wrow + g) * AP_ST + tg;

    for (int kt = 0; kt < nkt; ++kt) {
        const int kbase = kt * 64;
        const int buf = kt & 1;
        const float* sKt = smf + (buf ? OFF_K1 : OFF_K0);
        const float* bK = sKt + g * AK_ST + tg;

        cp_wait<1>();            // K_kt (and Q) ready
        __syncthreads();

        // ---- S = Q K^T ----
        float sacc[8][4];
#pragma unroll
        for (int n = 0; n < 8; ++n)
#pragma unroll
            for (int j = 0; j < 4; ++j) sacc[n][j] = 0.f;

#pragma unroll 4
        for (int kc = 0; kc < 16; ++kc) {
            const float* ap = aQ + kc * 8;
            uint32_t a0 = __float_as_uint(ap[0]);
            uint32_t a1 = __float_as_uint(ap[8 * AQ_ST]);
            uint32_t a2 = __float_as_uint(ap[4]);
            uint32_t a3 = __float_as_uint(ap[8 * AQ_ST + 4]);
#pragma unroll
            for (int n = 0; n < 8; ++n) {
                const float* bp = bK + n * 8 * AK_ST + kc * 8;
                mma_tf32_16n8k8(sacc[n][0], sacc[n][1], sacc[n][2], sacc[n][3],
                                a0, a1, a2, a3,
                                __float_as_uint(bp[0]), __float_as_uint(bp[4]));
            }
        }

        // prefetch next K (overlaps softmax + PV)
        if (kt + 1 < nkt) {
            const uint32_t ko = (kt & 1) ? OFF_K0 : OFF_K1;
            const float* ksrc = Kbase + (size_t)(kbase + 64) * PHD;
#pragma unroll
            for (int j = 0; j < 8; ++j) {
                int c = tid + 256 * j;
                int row = c >> 5, k4 = (c & 31) * 4;
                cp_async16(sb + (uint32_t)(ko + row * AK_ST + k4) * 4,
                           ksrc + (size_t)row * PHD + k4);
            }
        }
        cp_commit();

        // ---- mask + scale + online softmax ----
        const int grow0 = qbase + wrow + g;
        const int grow1 = grow0 + 8;
        const bool diag = (kbase + 63 > qbase);
        float tm0 = -1e30f, tm1 = -1e30f;
#pragma unroll
        for (int n = 0; n < 8; ++n) {
            const int gc = kbase + n * 8 + 2 * tg;
            if (diag) {
                sacc[n][0] = (gc     > grow0) ? -1e30f : sacc[n][0] * scale;
                sacc[n][1] = (gc + 1 > grow0) ? -1e30f : sacc[n][1] * scale;
                sacc[n][2] = (gc     > grow1) ? -1e30f : sacc[n][2] * scale;
                sacc[n][3] = (gc + 1 > grow1) ? -1e30f : sacc[n][3] * scale;
            } else {
                sacc[n][0] *= scale; sacc[n][1] *= scale;
                sacc[n][2] *= scale; sacc[n][3] *= scale;
            }
            tm0 = fmaxf(tm0, fmaxf(sacc[n][0], sacc[n][1]));
            tm1 = fmaxf(tm1, fmaxf(sacc[n][2], sacc[n][3]));
        }
        tm0 = fmaxf(tm0, __shfl_xor_sync(0xffffffffu, tm0, 1));
        tm0 = fmaxf(tm0, __shfl_xor_sync(0xffffffffu, tm0, 2));
        tm1 = fmaxf(tm1, __shfl_xor_sync(0xffffffffu, tm1, 1));
        tm1 = fmaxf(tm1, __shfl_xor_sync(0xffffffffu, tm1, 2));

        const float mn0 = fmaxf(m0, tm0);
        const float mn1 = fmaxf(m1, tm1);
        const float al0 = __expf(m0 - mn0);
        const float al1 = __expf(m1 - mn1);
        m0 = mn0; m1 = mn1;

        float rs0 = 0.f, rs1 = 0.f;
#pragma unroll
        for (int n = 0; n < 8; ++n) {
            float p0 = to_tf32(__expf(sacc[n][0] - mn0));
            float p1 = to_tf32(__expf(sacc[n][1] - mn0));
            float p2 = to_tf32(__expf(sacc[n][2] - mn1));
            float p3 = to_tf32(__expf(sacc[n][3] - mn1));
            rs0 += p0 + p1; rs1 += p2 + p3;
            *(float2*)&sP[(wrow + g) * AP_ST + n * 8 + 2 * tg] = make_float2(p0, p1);
            *(float2*)&sP[(wrow + g + 8) * AP_ST + n * 8 + 2 * tg] = make_float2(p2, p3);
        }
        rs0 += __shfl_xor_sync(0xffffffffu, rs0, 1);
        rs0 += __shfl_xor_sync(0xffffffffu, rs0, 2);
        rs1 += __shfl_xor_sync(0xffffffffu, rs1, 1);
        rs1 += __shfl_xor_sync(0xffffffffu, rs1, 2);
        l0 = l0 * al0 + rs0;
        l1 = l1 * al1 + rs1;

#pragma unroll
        for (int n = 0; n < 16; ++n) {
            oacc[n][0] *= al0; oacc[n][1] *= al0;
            oacc[n][2] *= al1; oacc[n][3] *= al1;
        }

        cp_wait<1>();            // V_kt ready
        __syncthreads();

        // ---- O += P V ----
#pragma unroll 2
        for (int c = 0; c < 8; ++c) {
            const float* ap = aP + c * 8;
            uint32_t a0 = __float_as_uint(ap[0]);
            uint32_t a1 = __float_as_uint(ap[8 * AP_ST]);
            uint32_t a2 = __float_as_uint(ap[4]);
            uint32_t a3 = __float_as_uint(ap[8 * AP_ST + 4]);
            const float* bv = sV + (c * 8 + tg) * AV_ST + g;
#pragma unroll
            for (int n = 0; n < 16; ++n) {
                const float* bp = bv + n * 8;
                mma_tf32_16n8k8(oacc[n][0], oacc[n][1], oacc[n][2], oacc[n][3],
                                a0, a1, a2, a3,
                                __float_as_uint(bp[0]),
                                __float_as_uint(bp[4 * AV_ST]));
            }
        }
        __syncthreads();          // everyone done reading sV (and sP)

        // prefetch next V (overlaps next S)
        if (kt + 1 < nkt) {
            const float* vsrc = Vbase + (size_t)(kbase + 64) * PHD;
#pragma unroll
            for (int j = 0; j < 8; ++j) {
                int c = tid + 256 * j;
                int row = c >> 5, k4 = (c & 31) * 4;
                cp_async16(sb + (uint32_t)(OFF_V + row * AV_ST + k4) * 4,
                           vsrc + (size_t)row * PHD + k4);
            }
        }
        cp_commit();
    }

    // ---- epilogue ----
    const float inv0 = 1.f / l0;
    const float inv1 = 1.f / l1;
    const int grow0 = qbase + wrow + g;
    float* y0 = Y + ((size_t)(b * PL + grow0)) * PE + h * PHD;
    float* y1 = Y + ((size_t)(b * PL + grow0 + 8)) * PE + h * PHD;
#pragma unroll
    for (int n = 0; n < 16; ++n) {
        const int col = n * 8 + 2 * tg;
        *(float2*)&y0[col] = make_float2(to_tf32(oacc[n][0] * inv0),
                                         to_tf32(oacc[n][1] * inv0));
        *(float2*)&y1[col] = make_float2(to_tf32(oacc[n][2] * inv1),
                                         to_tf32(oacc[n][3] * inv1));
    }
}

// ---------------------------------------------------------------------------
// launch
// ---------------------------------------------------------------------------
extern "C" void kernel_launch(void* const* d_in, const int* in_sizes, int n_in,
                              void* d_out, int out_size)
{
    (void)in_sizes; (void)n_in; (void)out_size;
    const float* x      = (const float*)d_in[0];
    const float* rope   = (const float*)d_in[1];
    const float* w_attn = (const float*)d_in[2];
    const float* w_proj = (const float*)d_in[3];
    float* out = (float*)d_out;

    float *q, *k, *v, *y, *xr, *war, *wpr;
    cudaGetSymbolAddress((void**)&q, g_q);
    cudaGetSymbolAddress((void**)&k, g_k);
    cudaGetSymbolAddress((void**)&v, g_v);
    cudaGetSymbolAddress((void**)&y, g_y);
    cudaGetSymbolAddress((void**)&xr, g_xr);
    cudaGetSymbolAddress((void**)&war, g_war);
    cudaGetSymbolAddress((void**)&wpr, g_wpr);

    cudaFuncSetAttribute(gemm_mma, cudaFuncAttributeMaxDynamicSharedMemorySize, GEMM_SMEM);
    cudaFuncSetAttribute(gemm_qkv_fused, cudaFuncAttributeMaxDynamicSharedMemorySize, GEMM_SMEM);
    cudaFuncSetAttribute(attn_mma_kernel, cudaFuncAttributeMaxDynamicSharedMemorySize, ATT_SMEM);

    // 0) pre-round GEMM inputs to tf32
    {
        int n4x = (PB * PL * PE) / 4;
        int n4a = (3 * PE * PE) / 4;
        int n4p = (PE * PE) / 4;
        round_tf32_kernel<<<n4x / 256, 256>>>((const float4*)x, (float4*)xr, n4x);
        round_tf32_kernel<<<n4a / 256, 256>>>((const float4*)w_attn, (float4*)war, n4a);
        round_tf32_kernel<<<n4p / 256, 256>>>((const float4*)w_proj, (float4*)wpr, n4p);
    }

    // 1) QKV projection + fused RoPE/split/round (tf32 HMMA)
    gemm_qkv_fused<<<dim3(3 * PE / BN, PB * PL / BM), 256, GEMM_SMEM>>>(
        xr, war, rope, q, k, v);

    // 2) causal flash attention (tf32 HMMA)
    attn_mma_kernel<<<dim3(PL / 128, PH, PB), 256, ATT_SMEM>>>(q, k, v, y);

    // 3) output projection (tf32 HMMA)
    gemm_mma<<<dim3(PE / BN, PB * PL / BM), 256, GEMM_SMEM>>>(
        y, wpr, out, PB * PL, PE, PE);
}